// round 3
// baseline (speedup 1.0000x reference)
#include <cuda_runtime.h>
#include <math.h>
#include <stdint.h>

#define MARGIN            0.3f
#define CLST_SCALE        0.8f
#define SEP_SCALE         0.08f
#define DIV_SCALE         0.01f
#define CONTRASTIVE_SCALE 0.1f

#define MAXC 1024   // max classes supported by scratch
#define MAXD 1024   // max feature dim for s-vector scratch
#define MAXR 32     // max prototype rows per class handled

__device__ float g_cls_n[MAXC];
__device__ float g_cls_sum[MAXC];
__device__ float g_sep_sum[MAXC];
__device__ float g_svec[MAXD];
__device__ float g_div_sum;
__device__ float g_ndv;
__device__ float g_diag;
__device__ int   g_mask_byte;

__device__ __forceinline__ float inff() { return __int_as_float(0x7f800000); }

// ---------------------------------------------------------------------------
// Kernel 0: zero scratch + detect valid_mask storage (1-byte bool vs int32).
// Only reads T bytes (= T/4 ints), which is safe under either layout.
// uint8 all-true  -> int read 0x01010101 (not 0/1) -> byte mode.
// int32 storage   -> all reads in {0,1}            -> int mode.
// ---------------------------------------------------------------------------
__global__ void k_zero(const unsigned char* mask, int T) {
    int tid = blockIdx.x * blockDim.x + threadIdx.x;
    if (tid < MAXC) { g_cls_n[tid] = 0.f; g_cls_sum[tid] = 0.f; g_sep_sum[tid] = 0.f; }
    if (tid < MAXD) { g_svec[tid] = 0.f; }
    if (tid == 0) {
        g_div_sum = 0.f; g_ndv = 0.f; g_diag = 0.f;
        int byte_mode = 0;
        const int* mi = (const int*)mask;
        int n = T >> 2;
        for (int i = 0; i < n; i++) {
            int v = mi[i];
            if (v != 0 && v != 1) { byte_mode = 1; break; }
        }
        g_mask_byte = byte_mode;
    }
}

// ---------------------------------------------------------------------------
// Kernel 1: streaming per-sample min kernel (the 65.5 MB pass).
// One warp per sample. Row staged into SMEM with coalesced float4 loads,
// then per-class mins (10 contiguous floats per class) from SMEM.
// ---------------------------------------------------------------------------
__global__ void k_min(const float* __restrict__ sims,
                      const int*   __restrict__ labels,
                      const int*   __restrict__ pidx,
                      int B, int C, int P) {
    extern __shared__ float dynsm[];                  // 8 warps * C*P floats
    __shared__ int scnt[MAXC];

    const int CP = C * P;
    for (int c = threadIdx.x; c < C && c < MAXC; c += blockDim.x)
        scnt[c] = pidx[2 * c + 1] - pidx[2 * c];
    __syncthreads();

    const int warp = threadIdx.x >> 5, lane = threadIdx.x & 31;
    const int warps_per_blk = blockDim.x >> 5;
    const int gw = blockIdx.x * warps_per_blk + warp;
    const int nw_total = gridDim.x * warps_per_blk;
    float* row = dynsm + (size_t)warp * CP;

    const bool vec_ok = ((CP & 3) == 0);

    for (int b = gw; b < B; b += nw_total) {
        const float* src = sims + (size_t)b * CP;
        if (vec_ok) {
            const float4* s4 = (const float4*)src;
            float4* r4 = (float4*)row;
            int n4 = CP >> 2;
            for (int i = lane; i < n4; i += 32) r4[i] = s4[i];
        } else {
            for (int i = lane; i < CP; i += 32) row[i] = src[i];
        }
        __syncwarp();

        const int lbl = labels[b];
        float own = inff(), other = inff();
        for (int c = lane; c < C; c += 32) {
            int cnt = (c < MAXC) ? scnt[c] : (pidx[2 * c + 1] - pidx[2 * c]);
            if (cnt > P) cnt = P;
            float m = inff();
            const float* pr = row + c * P;
            #pragma unroll 4
            for (int p = 0; p < cnt; p++) m = fminf(m, 1.0f - pr[p]);
            if (c == lbl) own = m;
            else          other = fminf(other, m);
        }
        #pragma unroll
        for (int o = 16; o; o >>= 1) {
            own   = fminf(own,   __shfl_xor_sync(0xFFFFFFFFu, own,   o));
            other = fminf(other, __shfl_xor_sync(0xFFFFFFFFu, other, o));
        }
        if (lane == 0) {
            float sep = fmaxf(MARGIN - other, 0.0f);
            atomicAdd(&g_cls_n[lbl],   1.0f);
            atomicAdd(&g_cls_sum[lbl], own);
            atomicAdd(&g_sep_sum[lbl], sep);
        }
        __syncwarp();
    }
}

// ---------------------------------------------------------------------------
// Kernel 2: per-class prototype work. Block per class.
// Normalizes the class's rows, accumulates Sum(pn) (valid rows) and
// Sum(|pn|^2) for the contrastive identity, and the same-class pair relu sum.
// ---------------------------------------------------------------------------
__global__ void k_proto(const float* __restrict__ protos,
                        const int*   __restrict__ pidx,
                        const unsigned char* __restrict__ mask,
                        int C, int T, int D) {
    extern __shared__ float pn[];            // [MAXR][D]
    __shared__ float s_pair;
    __shared__ float s_rnorm2[MAXR];
    __shared__ int   s_rvalid[MAXR];

    const int c = blockIdx.x;
    int rs = pidx[2 * c];
    int re = (c + 1 < C) ? pidx[2 * (c + 1)] : T;   // searchsorted class extent
    if (re > T) re = T;
    if (rs < 0) rs = 0;
    int nr = re - rs;
    if (nr > MAXR) nr = MAXR;
    if (nr < 0) nr = 0;

    const int warp = threadIdx.x >> 5, lane = threadIdx.x & 31;
    const int nwarp = blockDim.x >> 5;
    if (threadIdx.x == 0) s_pair = 0.f;
    const int mb = g_mask_byte;

    for (int r = warp; r < nr; r += nwarp) {
        const float* src = protos + (size_t)(rs + r) * D;
        float ss = 0.f;
        for (int d = lane; d < D; d += 32) {
            float v = src[d];
            pn[(size_t)r * D + d] = v;
            ss += v * v;
        }
        #pragma unroll
        for (int o = 16; o; o >>= 1) ss += __shfl_xor_sync(0xFFFFFFFFu, ss, o);
        float inv = 1.0f / fmaxf(sqrtf(ss), 1e-12f);
        for (int d = lane; d < D; d += 32) pn[(size_t)r * D + d] *= inv;
        if (lane == 0) {
            s_rnorm2[r] = ss * inv * inv;   // ==1 unless degenerate row
            int t = rs + r;
            int v = mb ? (int)mask[t] : ((const int*)mask)[t];
            s_rvalid[r] = (v != 0);
        }
    }
    __syncthreads();

    // Valid-row vector sum -> g_svec ; diag sum -> g_diag
    for (int d = threadIdx.x; d < D; d += blockDim.x) {
        float s = 0.f;
        for (int r = 0; r < nr; r++)
            if (s_rvalid[r]) s += pn[(size_t)r * D + d];
        atomicAdd(&g_svec[d], s);
    }
    if (threadIdx.x == 0) {
        float ds = 0.f;
        for (int r = 0; r < nr; r++) if (s_rvalid[r]) ds += s_rnorm2[r];
        atomicAdd(&g_diag, ds);
    }

    // Same-class off-diagonal pair relu sum (counted both orders: x2)
    const int npr = nr * (nr - 1) / 2;
    float local = 0.f;
    for (int k = warp; k < npr; k += nwarp) {
        int i = 0, rem = k;
        while (rem >= nr - 1 - i) { rem -= nr - 1 - i; i++; }
        int j = i + 1 + rem;
        float dot = 0.f;
        for (int d = lane; d < D; d += 32)
            dot += pn[(size_t)i * D + d] * pn[(size_t)j * D + d];
        #pragma unroll
        for (int o = 16; o; o >>= 1) dot += __shfl_xor_sync(0xFFFFFFFFu, dot, o);
        if (lane == 0) local += 2.0f * fmaxf(dot - 0.5f, 0.f);
    }
    if (lane == 0) atomicAdd(&s_pair, local);
    __syncthreads();

    if (threadIdx.x == 0) {
        int cnt = pidx[2 * c + 1] - pidx[2 * c];   // counts from proto_indices
        if (cnt > 1) {
            float npf = (float)cnt * (float)(cnt - 1);
            atomicAdd(&g_div_sum, s_pair / fmaxf(npf, 1.0f));
            atomicAdd(&g_ndv, 1.0f);
        }
    }
}

// ---------------------------------------------------------------------------
// Kernel 3: final reduction -> 5 outputs.
// ---------------------------------------------------------------------------
__global__ void k_final(const unsigned char* __restrict__ mask,
                        float* __restrict__ out, int C, int T, int D) {
    __shared__ float red[256];
    const int tid = threadIdx.x;

    float ca = 0.f, sa = 0.f, nv = 0.f;
    for (int c = tid; c < C; c += blockDim.x) {
        float n = g_cls_n[c];
        if (n > 0.f) {
            nv += 1.f;
            float nm = fmaxf(n, 1.f);
            ca += (1.0f / sqrtf(n + 1e-6f)) * (g_cls_sum[c] / nm);
            sa += g_sep_sum[c] / nm;
        }
    }
    float sn = 0.f;
    for (int d = tid; d < D; d += blockDim.x) { float v = g_svec[d]; sn += v * v; }

    float vc = 0.f;
    const int mb = g_mask_byte;
    for (int t = tid; t < T; t += blockDim.x) {
        int v = mb ? (int)mask[t] : ((const int*)mask)[t];
        vc += (v != 0) ? 1.f : 0.f;
    }

    // 5 block reductions
    float vals[5] = {ca, sa, nv, sn, vc};
    #pragma unroll
    for (int k = 0; k < 5; k++) {
        red[tid] = vals[k];
        __syncthreads();
        for (int s = blockDim.x >> 1; s; s >>= 1) {
            if (tid < s) red[tid] += red[tid + s];
            __syncthreads();
        }
        vals[k] = red[0];
        __syncthreads();
    }

    if (tid == 0) {
        float nvalid  = fmaxf(vals[2], 1.f);
        float cluster = vals[0] / nvalid * CLST_SCALE;
        float sep     = vals[1] / nvalid * SEP_SCALE;
        float divl    = g_div_sum / fmaxf(g_ndv, 1.f) * DIV_SCALE;
        float V       = vals[4];
        float nvp     = fmaxf(V * V - V, 1.f);
        float contr   = (vals[3] - g_diag) / nvp * CONTRASTIVE_SCALE;
        out[0] = cluster;
        out[1] = sep;
        out[2] = divl;
        out[3] = contr;
        out[4] = cluster + sep + divl + contr;
    }
}

extern "C" void kernel_launch(void* const* d_in, const int* in_sizes, int n_in,
                              void* d_out, int out_size) {
    const float* sims   = (const float*)d_in[0];
    const int*   labels = (const int*)  d_in[1];
    const float* protos = (const float*)d_in[2];
    const int*   pidx   = (const int*)  d_in[3];
    const unsigned char* mask = (const unsigned char*)d_in[4];

    const int B = in_sizes[1];
    const int C = in_sizes[3] / 2;
    const int T = in_sizes[4];
    const int D = in_sizes[2] / T;
    const int P = in_sizes[0] / (B * C);
    float* out = (float*)d_out;

    k_zero<<<(MAXC + 511) / 512, 512>>>(mask, T);

    const int CP = C * P;
    size_t smem1 = (size_t)8 * CP * sizeof(float);        // 8 warps/block
    k_min<<<592, 256, smem1>>>(sims, labels, pidx, B, C, P);

    size_t smem2 = (size_t)MAXR * D * sizeof(float);      // 32 KB for D=256
    k_proto<<<C, 128, smem2>>>(protos, pidx, mask, C, T, D);

    k_final<<<1, 256>>>(mask, out, C, T, D);
}

// round 4
// speedup vs baseline: 1.6404x; 1.6404x over previous
#include <cuda_runtime.h>
#include <math.h>
#include <stdint.h>

#define MARGIN            0.3f
#define CLST_SCALE        0.8f
#define SEP_SCALE         0.08f
#define DIV_SCALE         0.01f
#define CONTRASTIVE_SCALE 0.1f

#define MAXC 1024   // max classes supported by scratch
#define MAXD 1024   // max feature dim for s-vector scratch
#define MAXR 32     // max prototype rows per class
#define SCNT 128    // shared per-class count cache

struct Scratch {
    float cls_n[MAXC];
    float cls_sum[MAXC];
    float sep_sum[MAXC];
    float svec[MAXD];
    float div_sum;
    float ndv;
    float diag;
    unsigned int counter;
};
__device__ Scratch g;

__device__ __forceinline__ float inff() { return __int_as_float(0x7f800000); }

// ---------------------------------------------------------------------------
// One fused kernel.
//   blocks [0, C)        : per-class prototype work (normalize, pair relus,
//                          valid-row vector sum for the contrastive identity)
//   blocks [C, C+NMIN)   : streaming per-sample min pass (the 65.5 MB read)
//   last block to finish : final reduction -> 5 outputs (hot-L2, no extra launch)
// ---------------------------------------------------------------------------
__global__ void fused_kernel(const float* __restrict__ sims,
                             const int*   __restrict__ labels,
                             const float* __restrict__ protos,
                             const int*   __restrict__ pidx,
                             const unsigned char* __restrict__ mask,
                             float* __restrict__ out,
                             int B, int C, int P, int T, int D, int NMIN) {
    extern __shared__ float sm[];
    const int tid  = threadIdx.x;
    const int warp = tid >> 5, lane = tid & 31;
    const int nwarp = blockDim.x >> 5;

    // ---- mask storage detection (parallel, cheap, every block) -------------
    // uint8 storage of all-true bools reads as 0x01010101 ints (not 0/1).
    int bad = 0;
    {
        const int* mi = (const int*)mask;
        const int n = T >> 2;
        for (int i = tid; i < n; i += blockDim.x) {
            int v = mi[i];
            bad |= (v != 0 && v != 1);
        }
    }
    const int byte_mode = __syncthreads_or(bad);

    if ((int)blockIdx.x < C) {
        // =================== proto block for class c =======================
        float* pn = sm;                       // [MAXR][D]
        __shared__ float s_pair;
        __shared__ float s_rnorm2[MAXR];
        __shared__ int   s_rvalid[MAXR];

        const int c = blockIdx.x;
        int rs = pidx[2 * c];
        int re = (c + 1 < C) ? pidx[2 * (c + 1)] : T;
        if (re > T) re = T;
        if (rs < 0) rs = 0;
        int nr = re - rs;
        if (nr > MAXR) nr = MAXR;
        if (nr < 0) nr = 0;

        if (tid == 0) s_pair = 0.f;

        for (int r = warp; r < nr; r += nwarp) {
            const float* src = protos + (size_t)(rs + r) * D;
            float ss = 0.f;
            for (int d = lane; d < D; d += 32) {
                float v = src[d];
                pn[(size_t)r * D + d] = v;
                ss += v * v;
            }
            #pragma unroll
            for (int o = 16; o; o >>= 1) ss += __shfl_xor_sync(0xFFFFFFFFu, ss, o);
            float inv = 1.0f / fmaxf(sqrtf(ss), 1e-12f);
            for (int d = lane; d < D; d += 32) pn[(size_t)r * D + d] *= inv;
            if (lane == 0) {
                s_rnorm2[r] = ss * inv * inv;
                int t = rs + r;
                int v = byte_mode ? (int)mask[t] : ((const int*)mask)[t];
                s_rvalid[r] = (v != 0);
            }
        }
        __syncthreads();

        // valid-row vector sum -> g.svec ; diag -> g.diag
        for (int d = tid; d < D; d += blockDim.x) {
            float s = 0.f;
            for (int r = 0; r < nr; r++)
                if (s_rvalid[r]) s += pn[(size_t)r * D + d];
            atomicAdd(&g.svec[d], s);
        }
        if (tid == 0) {
            float ds = 0.f;
            for (int r = 0; r < nr; r++) if (s_rvalid[r]) ds += s_rnorm2[r];
            atomicAdd(&g.diag, ds);
        }

        // same-class off-diagonal relu pair sum (x2 for both orders)
        const int npr = nr * (nr - 1) / 2;
        float local = 0.f;
        for (int k = warp; k < npr; k += nwarp) {
            int i = 0, rem = k;
            while (rem >= nr - 1 - i) { rem -= nr - 1 - i; i++; }
            int j = i + 1 + rem;
            float dot = 0.f;
            for (int d = lane; d < D; d += 32)
                dot += pn[(size_t)i * D + d] * pn[(size_t)j * D + d];
            #pragma unroll
            for (int o = 16; o; o >>= 1) dot += __shfl_xor_sync(0xFFFFFFFFu, dot, o);
            if (lane == 0) local += 2.0f * fmaxf(dot - 0.5f, 0.f);
        }
        if (lane == 0 && local != 0.f) atomicAdd(&s_pair, local);
        __syncthreads();

        if (tid == 0) {
            int cnt = pidx[2 * c + 1] - pidx[2 * c];
            if (cnt > 1) {
                float npf = (float)cnt * (float)(cnt - 1);
                atomicAdd(&g.div_sum, s_pair / fmaxf(npf, 1.0f));
                atomicAdd(&g.ndv, 1.0f);
            }
        }
        __syncthreads();
    } else {
        // =================== streaming min blocks ==========================
        __shared__ int scnt[SCNT];
        const int CP = C * P;
        for (int c = tid; c < C && c < SCNT; c += blockDim.x)
            scnt[c] = pidx[2 * c + 1] - pidx[2 * c];
        __syncthreads();

        const int gw = ((int)blockIdx.x - C) * nwarp + warp;
        const int nw_total = NMIN * nwarp;
        float* row = sm + (size_t)warp * CP;
        const bool vec_ok = ((CP & 3) == 0);

        for (int b = gw; b < B; b += nw_total) {
            const float* src = sims + (size_t)b * CP;
            if (vec_ok) {
                const float4* s4 = (const float4*)src;
                float4* r4 = (float4*)row;
                int n4 = CP >> 2;
                for (int i = lane; i < n4; i += 32) r4[i] = s4[i];
            } else {
                for (int i = lane; i < CP; i += 32) row[i] = src[i];
            }
            __syncwarp();

            const int lbl = labels[b];
            // min(1-s) == 1 - max(s): track maxima, convert once.
            float ownmax = -inff(), othermax = -inff();
            for (int c = lane; c < C; c += 32) {
                int cnt = (c < SCNT) ? scnt[c] : (pidx[2 * c + 1] - pidx[2 * c]);
                if (cnt > P) cnt = P;
                float m = -inff();
                const float* pr = row + c * P;
                #pragma unroll 4
                for (int p = 0; p < cnt; p++) m = fmaxf(m, pr[p]);
                if (c == lbl) ownmax = m;
                else          othermax = fmaxf(othermax, m);
            }
            #pragma unroll
            for (int o = 16; o; o >>= 1) {
                ownmax   = fmaxf(ownmax,   __shfl_xor_sync(0xFFFFFFFFu, ownmax,   o));
                othermax = fmaxf(othermax, __shfl_xor_sync(0xFFFFFFFFu, othermax, o));
            }
            if (lane == 0) {
                float own   = 1.0f - ownmax;     // min distance, own class
                float other = 1.0f - othermax;   // min distance, other classes
                float sep   = fmaxf(MARGIN - other, 0.0f);
                atomicAdd(&g.cls_n[lbl],   1.0f);
                atomicAdd(&g.cls_sum[lbl], own);
                atomicAdd(&g.sep_sum[lbl], sep);
            }
            __syncwarp();
        }
        __syncthreads();
    }

    // =================== last-block finalize ===============================
    __threadfence();
    __shared__ unsigned int s_ord;
    if (tid == 0) s_ord = atomicAdd(&g.counter, 1u);
    __syncthreads();
    if (s_ord != (unsigned)(C + NMIN - 1)) return;
    __threadfence();

    __shared__ float red[256];
    float ca = 0.f, sa = 0.f, nv = 0.f;
    for (int c = tid; c < C; c += blockDim.x) {
        float n = g.cls_n[c];
        if (n > 0.f) {
            nv += 1.f;
            float nm = fmaxf(n, 1.f);
            ca += (1.0f / sqrtf(n + 1e-6f)) * (g.cls_sum[c] / nm);
            sa += g.sep_sum[c] / nm;
        }
    }
    float sn = 0.f;
    for (int d = tid; d < D; d += blockDim.x) { float v = g.svec[d]; sn += v * v; }
    float vc = 0.f;
    for (int t = tid; t < T; t += blockDim.x) {
        int v = byte_mode ? (int)mask[t] : ((const int*)mask)[t];
        vc += (v != 0) ? 1.f : 0.f;
    }

    float vals[5] = {ca, sa, nv, sn, vc};
    #pragma unroll
    for (int k = 0; k < 5; k++) {
        red[tid] = vals[k];
        __syncthreads();
        for (int s = blockDim.x >> 1; s; s >>= 1) {
            if (tid < s) red[tid] += red[tid + s];
            __syncthreads();
        }
        vals[k] = red[0];
        __syncthreads();
    }

    if (tid == 0) {
        float nvalid  = fmaxf(vals[2], 1.f);
        float cluster = vals[0] / nvalid * CLST_SCALE;
        float sep     = vals[1] / nvalid * SEP_SCALE;
        float divl    = g.div_sum / fmaxf(g.ndv, 1.f) * DIV_SCALE;
        float V       = vals[4];
        float nvp     = fmaxf(V * V - V, 1.f);
        float contr   = (vals[3] - g.diag) / nvp * CONTRASTIVE_SCALE;
        out[0] = cluster;
        out[1] = sep;
        out[2] = divl;
        out[3] = contr;
        out[4] = cluster + sep + divl + contr;
    }
}

extern "C" void kernel_launch(void* const* d_in, const int* in_sizes, int n_in,
                              void* d_out, int out_size) {
    const float* sims   = (const float*)d_in[0];
    const int*   labels = (const int*)  d_in[1];
    const float* protos = (const float*)d_in[2];
    const int*   pidx   = (const int*)  d_in[3];
    const unsigned char* mask = (const unsigned char*)d_in[4];

    const int B = in_sizes[1];
    const int C = in_sizes[3] / 2;
    const int T = in_sizes[4];
    const int D = in_sizes[2] / T;
    const int P = in_sizes[0] / (B * C);
    float* out = (float*)d_out;

    // zero the scratch (replaces the old k_zero launch)
    void* gp = nullptr;
    cudaGetSymbolAddress(&gp, g);
    cudaMemsetAsync(gp, 0, sizeof(Scratch), 0);

    const int CP = C * P;
    const int NMIN = 1036;                          // 148 SMs * 7 resident
    size_t smem_min   = (size_t)8 * CP * sizeof(float);
    size_t smem_proto = (size_t)MAXR * D * sizeof(float);
    size_t smem = smem_min > smem_proto ? smem_min : smem_proto;
    if (smem > 48 * 1024)
        cudaFuncSetAttribute(fused_kernel,
                             cudaFuncAttributeMaxDynamicSharedMemorySize,
                             (int)smem);

    fused_kernel<<<C + NMIN, 256, smem>>>(sims, labels, protos, pidx, mask,
                                          out, B, C, P, T, D, NMIN);
}